// round 1
// baseline (speedup 1.0000x reference)
#include <cuda_runtime.h>
#include <float.h>
#include <math.h>

// Problem constants: x = [B=16, C=2048, H=48, W=64] fp32
// Regions (H=48, W=64, L=3): 21 total
//   global 48x64; two 48x48 (j=0,16); six 32x32 (i in {0,16} x j in {0,16,32});
//   twelve 24x24 (i in {0,12,24} x j in {0,13,26,40})
#define B_  16
#define C_  2048
#define H_  48
#define W_  64
#define NPLANE (B_ * C_)
#define R_  21
#define EPS_ 1e-6f

// Scratch (allocation-free rule: __device__ globals)
__device__ float g_vecs[B_ * R_ * C_];    // [b][r][c]
__device__ float g_norms[B_ * R_];        // per (b, r) L2 norm

// Row-range index per region (6 distinct row ranges):
//  RR0=[0,48) RR1=[0,32) RR2=[16,48) RR3=[0,24) RR4=[12,36) RR5=[24,48)
__constant__ int REG_RR[R_] = {
    0,            // global
    0, 0,         // 48x48 @ j=0,16
    1, 1, 1,      // 32x32 rows [0,32)
    2, 2, 2,      // 32x32 rows [16,48)
    3, 3, 3, 3,   // 24x24 rows [0,24)
    4, 4, 4, 4,   // 24x24 rows [12,36)
    5, 5, 5, 5    // 24x24 rows [24,48)
};
__constant__ int REG_C0[R_] = {
    0,
    0, 16,
    0, 16, 32,
    0, 16, 32,
    0, 13, 26, 40,
    0, 13, 26, 40,
    0, 13, 26, 40
};
__constant__ int REG_C1[R_] = {
    64,
    48, 64,
    32, 48, 64,
    32, 48, 64,
    24, 37, 50, 64,
    24, 37, 50, 64,
    24, 37, 50, 64
};

// ---------------------------------------------------------------------------
// Kernel 1: one block per (b,c) plane. 64 threads = one per column.
// Each thread accumulates 6 row-segment maxes (breakpoints 0,12,16,24,32,36,48)
// over its column, combines into 6 row-range maxes in smem, then the 2 warps
// shuffle-reduce the 21 region column-ranges.
// ---------------------------------------------------------------------------
__global__ __launch_bounds__(64) void rpool_max_kernel(
    const float* __restrict__ x, float* __restrict__ vecs)
{
    const int plane = blockIdx.x;             // b * C + c
    const float* __restrict__ p = x + (size_t)plane * (H_ * W_);
    const int col = threadIdx.x;              // 0..63

    float s0 = -FLT_MAX, s1 = -FLT_MAX, s2 = -FLT_MAX;
    float s3 = -FLT_MAX, s4 = -FLT_MAX, s5 = -FLT_MAX;

    #pragma unroll
    for (int r = 0; r < 12; r++)  s0 = fmaxf(s0, p[r * W_ + col]);
    #pragma unroll
    for (int r = 12; r < 16; r++) s1 = fmaxf(s1, p[r * W_ + col]);
    #pragma unroll
    for (int r = 16; r < 24; r++) s2 = fmaxf(s2, p[r * W_ + col]);
    #pragma unroll
    for (int r = 24; r < 32; r++) s3 = fmaxf(s3, p[r * W_ + col]);
    #pragma unroll
    for (int r = 32; r < 36; r++) s4 = fmaxf(s4, p[r * W_ + col]);
    #pragma unroll
    for (int r = 36; r < 48; r++) s5 = fmaxf(s5, p[r * W_ + col]);

    __shared__ float rr[6][W_];
    const float m012 = fmaxf(fmaxf(s0, s1), s2);
    const float m345 = fmaxf(fmaxf(s3, s4), s5);
    rr[0][col] = fmaxf(m012, m345);                     // rows [0,48)
    rr[1][col] = fmaxf(m012, s3);                       // rows [0,32)
    rr[2][col] = fmaxf(fmaxf(s2, s3), fmaxf(s4, s5));   // rows [16,48)
    rr[3][col] = m012;                                  // rows [0,24)
    rr[4][col] = fmaxf(fmaxf(s1, s2), fmaxf(s3, s4));   // rows [12,36)
    rr[5][col] = m345;                                  // rows [24,48)
    __syncthreads();

    const int warp = threadIdx.x >> 5;
    const int lane = threadIdx.x & 31;
    const int b = plane >> 11;          // / C_
    const int c = plane & (C_ - 1);     // % C_

    for (int reg = warp; reg < R_; reg += 2) {
        const int ri = REG_RR[reg];
        const int c0 = REG_C0[reg];
        const int c1 = REG_C1[reg];
        float m = -FLT_MAX;
        for (int cc = c0 + lane; cc < c1; cc += 32)
            m = fmaxf(m, rr[ri][cc]);
        #pragma unroll
        for (int o = 16; o > 0; o >>= 1)
            m = fmaxf(m, __shfl_xor_sync(0xffffffffu, m, o));
        if (lane == 0)
            vecs[((size_t)(b * R_ + reg)) * C_ + c] = m;
    }
}

// ---------------------------------------------------------------------------
// Kernel 2: per-(b,r) L2 norm over C channels. grid = B*R blocks.
// ---------------------------------------------------------------------------
__global__ __launch_bounds__(256) void rpool_norm_kernel(
    const float* __restrict__ vecs, float* __restrict__ norms)
{
    const int br = blockIdx.x;  // b * R + r
    const float* __restrict__ v = vecs + (size_t)br * C_;
    const int tid = threadIdx.x;

    float acc = 0.f;
    #pragma unroll
    for (int i = tid; i < C_; i += 256) {
        const float t = v[i];
        acc += t * t;
    }
    // warp reduce
    #pragma unroll
    for (int o = 16; o > 0; o >>= 1)
        acc += __shfl_xor_sync(0xffffffffu, acc, o);

    __shared__ float wsum[8];
    const int lane = tid & 31, warp = tid >> 5;
    if (lane == 0) wsum[warp] = acc;
    __syncthreads();
    if (warp == 0) {
        float t = (lane < 8) ? wsum[lane] : 0.f;
        #pragma unroll
        for (int o = 4; o > 0; o >>= 1)
            t += __shfl_xor_sync(0xffffffffu, t, o);
        if (lane == 0) norms[br] = sqrtf(t);
    }
}

// ---------------------------------------------------------------------------
// Kernel 3: per-b aggregate. sum over regions of vec/(norm+eps), then
// L2-normalize over channels and write out[b][c].
// ---------------------------------------------------------------------------
__global__ __launch_bounds__(256) void rpool_agg_kernel(
    const float* __restrict__ vecs, const float* __restrict__ norms,
    float* __restrict__ out)
{
    const int b = blockIdx.x;
    const int tid = threadIdx.x;

    __shared__ float inv[R_];
    if (tid < R_) inv[tid] = 1.0f / (norms[b * R_ + tid] + EPS_);
    __syncthreads();

    float sreg[C_ / 256];   // 8 channels per thread
    float local = 0.f;
    #pragma unroll
    for (int i = 0; i < C_ / 256; i++) {
        const int c = tid + i * 256;
        float s = 0.f;
        #pragma unroll
        for (int r = 0; r < R_; r++)
            s += vecs[((size_t)(b * R_ + r)) * C_ + c] * inv[r];
        sreg[i] = s;
        local += s * s;
    }

    // block reduce local -> total
    #pragma unroll
    for (int o = 16; o > 0; o >>= 1)
        local += __shfl_xor_sync(0xffffffffu, local, o);
    __shared__ float wsum[8];
    const int lane = tid & 31, warp = tid >> 5;
    if (lane == 0) wsum[warp] = local;
    __syncthreads();
    __shared__ float s_invnorm;
    if (warp == 0) {
        float t = (lane < 8) ? wsum[lane] : 0.f;
        #pragma unroll
        for (int o = 4; o > 0; o >>= 1)
            t += __shfl_xor_sync(0xffffffffu, t, o);
        if (lane == 0) s_invnorm = 1.0f / (sqrtf(t) + EPS_);
    }
    __syncthreads();

    const float invn = s_invnorm;
    #pragma unroll
    for (int i = 0; i < C_ / 256; i++) {
        const int c = tid + i * 256;
        out[(size_t)b * C_ + c] = sreg[i] * invn;
    }
}

extern "C" void kernel_launch(void* const* d_in, const int* in_sizes, int n_in,
                              void* d_out, int out_size)
{
    const float* x = (const float*)d_in[0];
    float* out = (float*)d_out;

    float* vecs;
    float* norms;
    cudaGetSymbolAddress((void**)&vecs, g_vecs);
    cudaGetSymbolAddress((void**)&norms, g_norms);

    rpool_max_kernel<<<NPLANE, 64>>>(x, vecs);
    rpool_norm_kernel<<<B_ * R_, 256>>>(vecs, norms);
    rpool_agg_kernel<<<B_, 256>>>(vecs, norms, out);
}